// round 15
// baseline (speedup 1.0000x reference)
#include <cuda_runtime.h>
#include <cuda_fp16.h>
#include <cstdint>

// ---------------------------------------------------------------------------
// Round 15: attn softmax parallelized via 16-lane-segment shfl (no serialized
// t<16 block, one fewer barrier), residual loads hoisted; wvo+wtrans merged
// into one prep kernel. GEMMs unchanged from round 14.
// ---------------------------------------------------------------------------

#define M_TOK  131072
#define DMODEL 256
#define DQKV   384
#define DFF    1024
#define NWIN   8192

// ----------------------------- scratch -------------------------------------
__device__ __half g_xg [(size_t)M_TOK * DMODEL];
__device__ __half g_qkv[(size_t)M_TOK * DQKV];
__device__ __half g_h  [(size_t)M_TOK * DMODEL];
__device__ __half g_f  [(size_t)M_TOK * DFF];
__device__ __half g_bt_qkv[DQKV * DMODEL];   // [N][K]; rows 128.. = (Wv@Wo)^T
__device__ __half g_bt_1 [DFF * DMODEL];
__device__ __half g_bt_2 [DMODEL * DFF];
__device__ float  g_bqkv[DQKV];              // [bq | bk | bv@Wo]

__device__ __forceinline__ int src_row(int m) {
    int t  = m & 15;
    int w  = m >> 4;
    int wj = t & 3, wi = t >> 2;
    int sj = w & 31, si = (w >> 5) & 31, b = w >> 10;
    return ((b * 128) + si * 4 + wi) * 128 + sj * 4 + wj;
}

__device__ __forceinline__ uint32_t smem_u32(const void* p) {
    uint32_t a;
    asm("{ .reg .u64 t; cvta.to.shared.u64 t, %1; cvt.u32.u64 %0, t; }" : "=r"(a) : "l"(p));
    return a;
}
__device__ __forceinline__ void cp16(uint32_t s, const void* g) {
    asm volatile("cp.async.cg.shared.global [%0], [%1], 16;" :: "r"(s), "l"(g));
}
__device__ __forceinline__ void cp_commit() {
    asm volatile("cp.async.commit_group;" ::: "memory");
}
template <int N>
__device__ __forceinline__ void cp_wait() {
    asm volatile("cp.async.wait_group %0;" :: "n"(N) : "memory");
}
__device__ __forceinline__ void ldsm4(uint32_t& r0, uint32_t& r1, uint32_t& r2,
                                      uint32_t& r3, uint32_t addr) {
    asm volatile("ldmatrix.sync.aligned.m8n8.x4.shared.b16 {%0,%1,%2,%3}, [%4];"
                 : "=r"(r0), "=r"(r1), "=r"(r2), "=r"(r3) : "r"(addr));
}
__device__ __forceinline__ void mma_f16(float* c, const uint32_t* a, const uint32_t* b) {
    asm volatile(
        "mma.sync.aligned.m16n8k16.row.col.f32.f16.f16.f32 "
        "{%0,%1,%2,%3}, {%4,%5,%6,%7}, {%8,%9}, {%0,%1,%2,%3};\n"
        : "+f"(c[0]), "+f"(c[1]), "+f"(c[2]), "+f"(c[3])
        : "r"(a[0]), "r"(a[1]), "r"(a[2]), "r"(a[3]), "r"(b[0]), "r"(b[1]));
}
__device__ __forceinline__ uint32_t swz(uint32_t b) { return b ^ ((b >> 3) & 0x70); }

// ---------------- merged weight prep: transposes + Wvo/bvo -------------------
// blocks [0, 2432): transpose Wq/Wk/W1/W2 (half, [N][K] layout)
// blocks [2432, 2688): Wvo = Wv@Wo -> btq rows 128..383
// block  2688: bvo = bv@Wo -> bqkv[128..]
__global__ void __launch_bounds__(256)
prep_kernel(const float* __restrict__ Wq, const float* __restrict__ Wk,
            const float* __restrict__ Wv, const float* __restrict__ Wo,
            const float* __restrict__ W1, const float* __restrict__ W2,
            const float* __restrict__ bv,
            __half* btq, __half* bt1, __half* bt2, float* bqkv) {
    if (blockIdx.x < 2432) {
        int li = blockIdx.x * 256 + threadIdx.x;
        const float* W; __half* dst; int N, nofs, ldk;
        if (li < 16384)                  { W = Wq; dst = btq; N = 64;   nofs = 0;  ldk = 256;  }
        else if ((li -= 16384) < 16384)  { W = Wk; dst = btq; N = 64;   nofs = 64; ldk = 256;  }
        else if ((li -= 16384) < 262144) { W = W1; dst = bt1; N = 1024; nofs = 0;  ldk = 256;  }
        else if ((li -= 262144) < 262144){ W = W2; dst = bt2; N = 256;  nofs = 0;  ldk = 1024; }
        else return;
        int k = li / N, n = li % N;
        dst[(size_t)(nofs + n) * ldk + k] = __float2half_rn(W[li]);
    } else if (blockIdx.x < 2688) {
        const int d = blockIdx.x - 2432;
        const int j = threadIdx.x;
        const float* wrow = Wv + d * 256;
        float a0 = 0.f, a1 = 0.f, a2 = 0.f, a3 = 0.f;
        #pragma unroll 4
        for (int k = 0; k < 256; k += 4) {
            a0 += wrow[k + 0] * Wo[(k + 0) * 256 + j];
            a1 += wrow[k + 1] * Wo[(k + 1) * 256 + j];
            a2 += wrow[k + 2] * Wo[(k + 2) * 256 + j];
            a3 += wrow[k + 3] * Wo[(k + 3) * 256 + j];
        }
        btq[(size_t)(128 + j) * 256 + d] = __float2half_rn((a0 + a1) + (a2 + a3));
    } else {
        const int j = threadIdx.x;
        float a = 0.f;
        for (int k = 0; k < 256; k++) a += bv[k] * Wo[k * 256 + j];
        bqkv[128 + j] = a;
    }
}

// ----------------------------- gather + round --------------------------------
__global__ void gather_kernel(const float* __restrict__ x, __half* __restrict__ xg) {
    const float4* x4 = reinterpret_cast<const float4*>(x);
    int base = blockIdx.x * 1024 + threadIdx.x;
    #pragma unroll
    for (int i = 0; i < 4; i++) {
        int idx = base + i * 256;
        int m = idx >> 6, c = idx & 63;
        float4 v = x4[src_row(m) * 64 + c];
        __half2 h0 = __floats2half2_rn(v.x, v.y);
        __half2 h1 = __floats2half2_rn(v.z, v.w);
        uint2 u;
        u.x = *reinterpret_cast<uint32_t*>(&h0);
        u.y = *reinterpret_cast<uint32_t*>(&h1);
        *reinterpret_cast<uint2*>(xg + (size_t)idx * 4) = u;
    }
}

// ------------------- B-resident GEMM (K=256, MT M-tiles/CTA) -----------------
#define BC_ACHUNK 16384
#define BC_BBYTES 65536
#define BC_SMEM   (BC_BBYTES + 3 * BC_ACHUNK)
template <bool RELU, int MT>
__global__ void __launch_bounds__(256, 2)
gemm_bc(const __half* __restrict__ A, const __half* __restrict__ Bt,
        const float* __restrict__ bias, __half* __restrict__ C, int N)
{
    constexpr int K = 256;
    extern __shared__ char smem[];
    const uint32_t sb = smem_u32(smem);
    const uint32_t SM_B = sb;
    const uint32_t SM_A = sb + BC_BBYTES;

    const int tid  = threadIdx.x;
    const int lane = tid & 31, warp = tid >> 5;
    const int wm = warp >> 2, wn = warp & 3;
    const int lq = lane >> 2, lr = lane & 3;
    const int row00 = blockIdx.y * (128 * MT);
    const int n0    = blockIdx.x * 128;

    const int r_ld = tid >> 3;
    const int cseg = tid & 7;
    const uint32_t sOff = swz(r_ld * 128 + cseg * 16);

    {
        const size_t bRow0 = (size_t)(n0 + r_ld) * K;
        #pragma unroll
        for (int kt = 0; kt < 4; kt++) {
            const int kofs = kt * 64 + cseg * 8;
            #pragma unroll
            for (int i = 0; i < 4; i++)
                cp16(SM_B + kt * BC_ACHUNK + sOff + i * 4096,
                     Bt + bRow0 + (size_t)i * 32 * K + kofs);
        }
        cp_commit();
    }

    auto load_A = [&](int it, int buf) {
        const int m = it >> 2, kt = it & 3;
        const int kofs = kt * 64 + cseg * 8;
        const size_t aRow0 = (size_t)(row00 + m * 128 + r_ld) * K;
        const uint32_t aBase = SM_A + buf * BC_ACHUNK;
        #pragma unroll
        for (int i = 0; i < 4; i++)
            cp16(aBase + sOff + i * 4096, A + aRow0 + (size_t)i * 32 * K + kofs);
        cp_commit();
    };

    const int quad = lane >> 3, r8 = lane & 7;
    const int aRowL  = wm * 64 + (quad & 1) * 8 + r8;
    const int aKoffB = (quad >> 1) * 16;
    const int bRowL  = wn * 32 + (quad >> 1) * 8 + r8;
    const int bKoffB = (quad & 1) * 16;

    float acc[4][4][4];

    auto compute = [&](int buf, int kt) {
        const uint32_t aBase = SM_A + buf * BC_ACHUNK;
        const uint32_t bBase = SM_B + kt * BC_ACHUNK;
        #pragma unroll
        for (int ks = 0; ks < 4; ks++) {
            uint32_t af[4][4], bf[2][4];
            #pragma unroll
            for (int mi = 0; mi < 4; mi++) {
                int row = aRowL + mi * 16;
                ldsm4(af[mi][0], af[mi][1], af[mi][2], af[mi][3],
                      aBase + swz(row * 128 + ks * 32 + aKoffB));
            }
            #pragma unroll
            for (int nt = 0; nt < 2; nt++) {
                int row = bRowL + nt * 16;
                ldsm4(bf[nt][0], bf[nt][1], bf[nt][2], bf[nt][3],
                      bBase + swz(row * 128 + ks * 32 + bKoffB));
            }
            #pragma unroll
            for (int mi = 0; mi < 4; mi++) {
                #pragma unroll
                for (int nt = 0; nt < 2; nt++) {
                    mma_f16(acc[mi][nt * 2 + 0], af[mi], &bf[nt][0]);
                    mma_f16(acc[mi][nt * 2 + 1], af[mi], &bf[nt][2]);
                }
            }
        }
    };

    auto epilogue = [&](int m) {
        #pragma unroll
        for (int mi = 0; mi < 4; mi++) {
            #pragma unroll
            for (int ni = 0; ni < 4; ni++) {
                const int r0 = row00 + m * 128 + wm * 64 + mi * 16 + lq;
                const int c0 = n0 + wn * 32 + ni * 8 + 2 * lr;
                const float b0 = __ldg(bias + c0), b1 = __ldg(bias + c0 + 1);
                float v0 = acc[mi][ni][0] + b0;
                float v1 = acc[mi][ni][1] + b1;
                float v2 = acc[mi][ni][2] + b0;
                float v3 = acc[mi][ni][3] + b1;
                if (RELU) {
                    v0 = fmaxf(v0, 0.f); v1 = fmaxf(v1, 0.f);
                    v2 = fmaxf(v2, 0.f); v3 = fmaxf(v3, 0.f);
                }
                *reinterpret_cast<__half2*>(C + (size_t)r0 * N + c0) =
                    __floats2half2_rn(v0, v1);
                *reinterpret_cast<__half2*>(C + (size_t)(r0 + 8) * N + c0) =
                    __floats2half2_rn(v2, v3);
            }
        }
    };

    load_A(0, 0);
    load_A(1, 1);
    const int IT = MT * 4;
    for (int it = 0; it < IT; it++) {
        const int kt = it & 3, buf = it % 3;
        if (kt == 0) {
            #pragma unroll
            for (int mi = 0; mi < 4; mi++)
                #pragma unroll
                for (int ni = 0; ni < 4; ni++)
                    #pragma unroll
                    for (int j = 0; j < 4; j++) acc[mi][ni][j] = 0.f;
        }
        cp_wait<1>();
        __syncthreads();
        if (it + 2 < IT) load_A(it + 2, (it + 2) % 3);
        else cp_commit();
        compute(buf, kt);
        if (kt == 3) epilogue(it >> 2);
    }
}

// --------- fused GEMM + bias + residual + LayerNorm (+scatter), K-deep -------
#define GL_ASTG  16384
#define GL_BSTG  32768
#define GL_STG   (GL_ASTG + GL_BSTG)
#define GL_SMEM  (3 * GL_STG)
template <int K, bool SCATTER, typename OutT>
__global__ void __launch_bounds__(512, 1)
gemm_ln(const __half* __restrict__ A, const __half* __restrict__ Bt,
        const float* __restrict__ bias, const __half* __restrict__ Hres,
        const float* __restrict__ gamma, const float* __restrict__ beta,
        OutT* __restrict__ out)
{
    extern __shared__ char smem[];
    const uint32_t sb = smem_u32(smem);

    const int tid  = threadIdx.x;
    const int lane = tid & 31, warp = tid >> 5;
    const int wm = warp >> 2, wn = warp & 3;
    const int lq = lane >> 2, lr = lane & 3;
    const int row0 = blockIdx.x * 128;

    float acc[2][8][4];
    #pragma unroll
    for (int mi = 0; mi < 2; mi++)
        #pragma unroll
        for (int ni = 0; ni < 8; ni++)
            #pragma unroll
            for (int j = 0; j < 4; j++) acc[mi][ni][j] = 0.f;

    const int r_ld = tid >> 3;
    const int cseg = tid & 7;
    const uint32_t sOff = swz(r_ld * 128 + cseg * 16);

    auto load_stage = [&](int kt, int buf) {
        const int kofs = kt * 64 + cseg * 8;
        const uint32_t aBase = sb + buf * GL_STG;
        const uint32_t bBase = aBase + GL_ASTG;
        #pragma unroll
        for (int i = 0; i < 2; i++)
            cp16(aBase + sOff + i * 8192,
                 A + (size_t)(row0 + r_ld + i * 64) * K + kofs);
        #pragma unroll
        for (int i = 0; i < 4; i++)
            cp16(bBase + sOff + i * 8192,
                 Bt + (size_t)(r_ld + i * 64) * K + kofs);
        cp_commit();
    };

    const int quad = lane >> 3, r8 = lane & 7;
    const int aRowL  = wm * 32 + (quad & 1) * 8 + r8;
    const int aKoffB = (quad >> 1) * 16;
    const int bRowL  = wn * 64 + (quad >> 1) * 8 + r8;
    const int bKoffB = (quad & 1) * 16;

    auto compute = [&](int buf) {
        const uint32_t aBase = sb + buf * GL_STG;
        const uint32_t bBase = aBase + GL_ASTG;
        #pragma unroll
        for (int ks = 0; ks < 4; ks++) {
            uint32_t af[2][4], bf[4][4];
            #pragma unroll
            for (int mi = 0; mi < 2; mi++) {
                int row = aRowL + mi * 16;
                ldsm4(af[mi][0], af[mi][1], af[mi][2], af[mi][3],
                      aBase + swz(row * 128 + ks * 32 + aKoffB));
            }
            #pragma unroll
            for (int nt = 0; nt < 4; nt++) {
                int row = bRowL + nt * 16;
                ldsm4(bf[nt][0], bf[nt][1], bf[nt][2], bf[nt][3],
                      bBase + swz(row * 128 + ks * 32 + bKoffB));
            }
            #pragma unroll
            for (int mi = 0; mi < 2; mi++) {
                #pragma unroll
                for (int nt = 0; nt < 4; nt++) {
                    mma_f16(acc[mi][nt * 2 + 0], af[mi], &bf[nt][0]);
                    mma_f16(acc[mi][nt * 2 + 1], af[mi], &bf[nt][2]);
                }
            }
        }
    };

    load_stage(0, 0);
    load_stage(1, 1);
    const int KT = K >> 6;
    for (int kt = 0; kt < KT; kt++) {
        cp_wait<1>();
        __syncthreads();
        if (kt + 2 < KT) load_stage(kt + 2, (kt + 2) % 3);
        else cp_commit();
        compute(kt % 3);
    }

    __syncthreads();
    float2* rowred = reinterpret_cast<float2*>(smem);

    #pragma unroll
    for (int mi = 0; mi < 2; mi++) {
        #pragma unroll
        for (int rs = 0; rs < 2; rs++) {
            const int row_l = wm * 32 + mi * 16 + lq + rs * 8;
            const int grow  = row0 + row_l;
            float s = 0.f, sq = 0.f;
            #pragma unroll
            for (int ni = 0; ni < 8; ni++) {
                const int c0 = wn * 64 + ni * 8 + 2 * lr;
                __half2 h2 = *reinterpret_cast<const __half2*>(
                    Hres + (size_t)grow * DMODEL + c0);
                float2 fh = __half22float2(h2);
                float v0 = acc[mi][ni][rs * 2 + 0] + fh.x + __ldg(bias + c0);
                float v1 = acc[mi][ni][rs * 2 + 1] + fh.y + __ldg(bias + c0 + 1);
                acc[mi][ni][rs * 2 + 0] = v0;
                acc[mi][ni][rs * 2 + 1] = v1;
                s += v0 + v1; sq += v0 * v0 + v1 * v1;
            }
            s  += __shfl_xor_sync(0xffffffffu, s, 1);
            sq += __shfl_xor_sync(0xffffffffu, sq, 1);
            s  += __shfl_xor_sync(0xffffffffu, s, 2);
            sq += __shfl_xor_sync(0xffffffffu, sq, 2);
            if (lr == 0) rowred[row_l * 4 + wn] = make_float2(s, sq);
        }
    }
    __syncthreads();

    #pragma unroll
    for (int mi = 0; mi < 2; mi++) {
        #pragma unroll
        for (int rs = 0; rs < 2; rs++) {
            const int row_l = wm * 32 + mi * 16 + lq + rs * 8;
            const int grow  = row0 + row_l;
            float2 t0 = rowred[row_l * 4 + 0];
            float2 t1 = rowred[row_l * 4 + 1];
            float2 t2 = rowred[row_l * 4 + 2];
            float2 t3 = rowred[row_l * 4 + 3];
            const float s  = t0.x + t1.x + t2.x + t3.x;
            const float sq = t0.y + t1.y + t2.y + t3.y;
            const float mean = s * (1.f / DMODEL);
            const float var  = sq * (1.f / DMODEL) - mean * mean;
            const float rstd = rsqrtf(var + 1e-5f);
            const int orow = SCATTER ? src_row(grow) : grow;
            OutT* op = out + (size_t)orow * DMODEL;
            #pragma unroll
            for (int ni = 0; ni < 8; ni++) {
                const int c0 = wn * 64 + ni * 8 + 2 * lr;
                float o0 = (acc[mi][ni][rs * 2 + 0] - mean) * rstd * __ldg(gamma + c0)
                         + __ldg(beta + c0);
                float o1 = (acc[mi][ni][rs * 2 + 1] - mean) * rstd * __ldg(gamma + c0 + 1)
                         + __ldg(beta + c0 + 1);
                if (sizeof(OutT) == 2) {
                    *reinterpret_cast<__half2*>((__half*)op + c0) =
                        __floats2half2_rn(o0, o1);
                } else {
                    *reinterpret_cast<float2*>((float*)op + c0) = make_float2(o0, o1);
                }
            }
        }
    }
}

// ------------- attention + residual + LN1 (per window) -----------------------
// Parallel softmax: per-thread score + 16-lane-segment shfl reductions.
__global__ void __launch_bounds__(256)
attn_kernel(const __half* __restrict__ qkv, const __half* __restrict__ xg,
            const float* __restrict__ bo,
            const float* __restrict__ g1, const float* __restrict__ b1,
            __half* __restrict__ h) {
    __shared__ uint32_t qs [16 * 32];
    __shared__ uint32_t ksT[32 * 17];
    __shared__ uint32_t vs [16 * 128];
    __shared__ float    sc [16][17];

    const int w = blockIdx.x, t = threadIdx.x;
    const __half* base = qkv + (size_t)w * 16 * DQKV;

    {   // q,k staging
        int which = t >> 7;
        int vi = t & 127;
        int r = vi >> 3, c8 = (vi & 7) * 8;
        uint4 raw = *reinterpret_cast<const uint4*>(base + r * DQKV + which * 64 + c8);
        uint32_t u[4] = {raw.x, raw.y, raw.z, raw.w};
        if (which == 0) {
            #pragma unroll
            for (int p = 0; p < 4; p++) qs[r * 32 + c8 / 2 + p] = u[p];
        } else {
            #pragma unroll
            for (int p = 0; p < 4; p++) ksT[(c8 / 2 + p) * 17 + r] = u[p];
        }
    }
    #pragma unroll
    for (int it = 0; it < 2; it++) {       // v staging
        int vi = t + it * 256;
        int r = vi >> 5, c8 = (vi & 31) * 8;
        uint4 raw = *reinterpret_cast<const uint4*>(base + r * DQKV + 128 + c8);
        vs[r * 128 + c8 / 2 + 0] = raw.x;
        vs[r * 128 + c8 / 2 + 1] = raw.y;
        vs[r * 128 + c8 / 2 + 2] = raw.z;
        vs[r * 128 + c8 / 2 + 3] = raw.w;
    }

    // hoisted residual loads (gmem, independent of smem staging)
    const int tp  = t >> 5;            // warp id: tokens tp, tp+8
    const int cp0 = t & 31;            // lane
    float2 resid[2][4];
    #pragma unroll
    for (int s2 = 0; s2 < 2; s2++) {
        const __half* xrow = xg + (size_t)(w * 16 + tp + s2 * 8) * DMODEL;
        #pragma unroll
        for (int j = 0; j < 4; j++) {
            const int c = 2 * (cp0 + 32 * j);
            resid[s2][j] = __half22float2(
                *reinterpret_cast<const __half2*>(xrow + c));
        }
    }
    __syncthreads();

    {   // scores + parallel softmax: thread (qi,kj)
        const int qi = t >> 4, kj = t & 15;
        float s = 0.f;
        #pragma unroll
        for (int e2 = 0; e2 < 32; e2++) {
            float2 q = __half22float2(*reinterpret_cast<const __half2*>(&qs[qi * 32 + e2]));
            float2 k = __half22float2(*reinterpret_cast<const __half2*>(&ksT[e2 * 17 + kj]));
            s += q.x * k.x + q.y * k.y;
        }
        s *= 0.125f;
        // max over the 16-lane segment holding this row
        float mx = s;
        #pragma unroll
        for (int off = 8; off; off >>= 1)
            mx = fmaxf(mx, __shfl_xor_sync(0xffffffffu, mx, off));
        const float e = __expf(s - mx);
        float sum = e;
        #pragma unroll
        for (int off = 8; off; off >>= 1)
            sum += __shfl_xor_sync(0xffffffffu, sum, off);
        sc[qi][kj] = e * (1.f / sum);
    }
    __syncthreads();

    {   // AV + residual + LN1
        float accx[2][4], accy[2][4];
        #pragma unroll
        for (int s2 = 0; s2 < 2; s2++)
            #pragma unroll
            for (int j = 0; j < 4; j++) { accx[s2][j] = 0.f; accy[s2][j] = 0.f; }

        #pragma unroll
        for (int kk = 0; kk < 16; kk++) {
            const float a0 = sc[tp][kk];
            const float a1 = sc[tp + 8][kk];
            #pragma unroll
            for (int j = 0; j < 4; j++) {
                float2 v = __half22float2(
                    *reinterpret_cast<const __half2*>(&vs[kk * 128 + cp0 + 32 * j]));
                accx[0][j] += a0 * v.x; accy[0][j] += a0 * v.y;
                accx[1][j] += a1 * v.x; accy[1][j] += a1 * v.y;
            }
        }

        #pragma unroll
        for (int s2 = 0; s2 < 2; s2++) {
            const int grow = w * 16 + tp + s2 * 8;
            float s = 0.f, sq = 0.f;
            #pragma unroll
            for (int j = 0; j < 4; j++) {
                const int c = 2 * (cp0 + 32 * j);
                float v0 = accx[s2][j] + resid[s2][j].x + __ldg(bo + c);
                float v1 = accy[s2][j] + resid[s2][j].y + __ldg(bo + c + 1);
                accx[s2][j] = v0; accy[s2][j] = v1;
                s += v0 + v1; sq += v0 * v0 + v1 * v1;
            }
            #pragma unroll
            for (int off = 16; off; off >>= 1) {
                s  += __shfl_xor_sync(0xffffffffu, s,  off);
                sq += __shfl_xor_sync(0xffffffffu, sq, off);
            }
            const float mean = s * (1.f / DMODEL);
            const float var  = sq * (1.f / DMODEL) - mean * mean;
            const float rstd = rsqrtf(var + 1e-5f);
            __half* hrow = h + (size_t)grow * DMODEL;
            #pragma unroll
            for (int j = 0; j < 4; j++) {
                const int c = 2 * (cp0 + 32 * j);
                float o0 = (accx[s2][j] - mean) * rstd * __ldg(g1 + c) + __ldg(b1 + c);
                float o1 = (accy[s2][j] - mean) * rstd * __ldg(g1 + c + 1) + __ldg(b1 + c + 1);
                *reinterpret_cast<__half2*>(hrow + c) = __floats2half2_rn(o0, o1);
            }
        }
    }
}

// ------------------------------ launch --------------------------------------
extern "C" void kernel_launch(void* const* d_in, const int* in_sizes, int n_in,
                              void* d_out, int out_size) {
    const float* x   = (const float*)d_in[0];
    const float* Wq  = (const float*)d_in[1];
    const float* bq  = (const float*)d_in[2];
    const float* Wk  = (const float*)d_in[3];
    const float* bk  = (const float*)d_in[4];
    const float* Wv  = (const float*)d_in[5];
    const float* bv  = (const float*)d_in[6];
    const float* Wo  = (const float*)d_in[7];
    const float* bo  = (const float*)d_in[8];
    const float* g1  = (const float*)d_in[9];
    const float* b1  = (const float*)d_in[10];
    const float* W1  = (const float*)d_in[11];
    const float* bf1 = (const float*)d_in[12];
    const float* W2  = (const float*)d_in[13];
    const float* bf2 = (const float*)d_in[14];
    const float* g2  = (const float*)d_in[15];
    const float* b2  = (const float*)d_in[16];
    float* out = (float*)d_out;

    void *pxg, *pqkv, *ph, *pf, *pbtq, *pbt1, *pbt2, *pbq;
    cudaGetSymbolAddress(&pxg, g_xg);
    cudaGetSymbolAddress(&pqkv, g_qkv);
    cudaGetSymbolAddress(&ph,  g_h);
    cudaGetSymbolAddress(&pf,  g_f);
    cudaGetSymbolAddress(&pbtq, g_bt_qkv);
    cudaGetSymbolAddress(&pbt1, g_bt_1);
    cudaGetSymbolAddress(&pbt2, g_bt_2);
    cudaGetSymbolAddress(&pbq,  g_bqkv);
    __half* xg = (__half*)pxg; __half* qkv = (__half*)pqkv;
    __half* h = (__half*)ph; __half* f = (__half*)pf;
    __half* btq = (__half*)pbtq;
    __half* bt1 = (__half*)pbt1; __half* bt2 = (__half*)pbt2;
    float* bqkv = (float*)pbq;

    cudaFuncSetAttribute(gemm_bc<false, 4>, cudaFuncAttributeMaxDynamicSharedMemorySize, BC_SMEM);
    cudaFuncSetAttribute(gemm_bc<true,  8>, cudaFuncAttributeMaxDynamicSharedMemorySize, BC_SMEM);
    cudaFuncSetAttribute(gemm_ln<1024, true, float>, cudaFuncAttributeMaxDynamicSharedMemorySize, GL_SMEM);

    // (1) weight prep: transposes + Wvo/bvo
    prep_kernel<<<2689, 256>>>(Wq, Wk, Wv, Wo, W1, W2, bv, btq, bt1, bt2, bqkv);

    cudaMemcpyAsync(bqkv,      bq, 64 * sizeof(float), cudaMemcpyDeviceToDevice);
    cudaMemcpyAsync(bqkv + 64, bk, 64 * sizeof(float), cudaMemcpyDeviceToDevice);

    // (2) gather
    gather_kernel<<<NWIN, 256>>>(x, xg);

    // (3) qkv = xg @ [Wq | Wk | Wv@Wo]^T + [bq|bk|bvo]
    gemm_bc<false, 4><<<dim3(3, M_TOK / 512), 256, BC_SMEM>>>(xg, btq, bqkv, qkv, DQKV);

    // (4, profiled slot) attention + residual + LN1 -> h
    attn_kernel<<<NWIN, 256>>>(qkv, xg, bo, g1, b1, h);

    // (5) f = relu(h @ W1 + bf1)
    gemm_bc<true, 8><<<dim3(8, M_TOK / 1024), 256, BC_SMEM>>>(h, bt1, bf1, f, DFF);

    // (6) out = scatter(LN(h + f @ W2 + bf2))
    gemm_ln<1024, true, float><<<M_TOK / 128, 512, GL_SMEM>>>(
        f, bt2, bf2, h, g2, b2, out);
}

// round 16
// speedup vs baseline: 1.0073x; 1.0073x over previous
#include <cuda_runtime.h>
#include <cuda_fp16.h>
#include <cstdint>

// ---------------------------------------------------------------------------
// Round 16: attn reverted to round-14 body (proven best) + __launch_bounds__
// (256,5) to recover occupancy (round-15 profile: 64 regs, occ 47%).
// Merged prep kernel kept. GEMMs unchanged.
// ---------------------------------------------------------------------------

#define M_TOK  131072
#define DMODEL 256
#define DQKV   384
#define DFF    1024
#define NWIN   8192

// ----------------------------- scratch -------------------------------------
__device__ __half g_xg [(size_t)M_TOK * DMODEL];
__device__ __half g_qkv[(size_t)M_TOK * DQKV];
__device__ __half g_h  [(size_t)M_TOK * DMODEL];
__device__ __half g_f  [(size_t)M_TOK * DFF];
__device__ __half g_bt_qkv[DQKV * DMODEL];   // [N][K]; rows 128.. = (Wv@Wo)^T
__device__ __half g_bt_1 [DFF * DMODEL];
__device__ __half g_bt_2 [DMODEL * DFF];
__device__ float  g_bqkv[DQKV];              // [bq | bk | bv@Wo]

__device__ __forceinline__ int src_row(int m) {
    int t  = m & 15;
    int w  = m >> 4;
    int wj = t & 3, wi = t >> 2;
    int sj = w & 31, si = (w >> 5) & 31, b = w >> 10;
    return ((b * 128) + si * 4 + wi) * 128 + sj * 4 + wj;
}

__device__ __forceinline__ uint32_t smem_u32(const void* p) {
    uint32_t a;
    asm("{ .reg .u64 t; cvta.to.shared.u64 t, %1; cvt.u32.u64 %0, t; }" : "=r"(a) : "l"(p));
    return a;
}
__device__ __forceinline__ void cp16(uint32_t s, const void* g) {
    asm volatile("cp.async.cg.shared.global [%0], [%1], 16;" :: "r"(s), "l"(g));
}
__device__ __forceinline__ void cp_commit() {
    asm volatile("cp.async.commit_group;" ::: "memory");
}
template <int N>
__device__ __forceinline__ void cp_wait() {
    asm volatile("cp.async.wait_group %0;" :: "n"(N) : "memory");
}
__device__ __forceinline__ void ldsm4(uint32_t& r0, uint32_t& r1, uint32_t& r2,
                                      uint32_t& r3, uint32_t addr) {
    asm volatile("ldmatrix.sync.aligned.m8n8.x4.shared.b16 {%0,%1,%2,%3}, [%4];"
                 : "=r"(r0), "=r"(r1), "=r"(r2), "=r"(r3) : "r"(addr));
}
__device__ __forceinline__ void mma_f16(float* c, const uint32_t* a, const uint32_t* b) {
    asm volatile(
        "mma.sync.aligned.m16n8k16.row.col.f32.f16.f16.f32 "
        "{%0,%1,%2,%3}, {%4,%5,%6,%7}, {%8,%9}, {%0,%1,%2,%3};\n"
        : "+f"(c[0]), "+f"(c[1]), "+f"(c[2]), "+f"(c[3])
        : "r"(a[0]), "r"(a[1]), "r"(a[2]), "r"(a[3]), "r"(b[0]), "r"(b[1]));
}
__device__ __forceinline__ uint32_t swz(uint32_t b) { return b ^ ((b >> 3) & 0x70); }

// ---------------- merged weight prep: transposes + Wvo/bvo -------------------
__global__ void __launch_bounds__(256)
prep_kernel(const float* __restrict__ Wq, const float* __restrict__ Wk,
            const float* __restrict__ Wv, const float* __restrict__ Wo,
            const float* __restrict__ W1, const float* __restrict__ W2,
            const float* __restrict__ bv,
            __half* btq, __half* bt1, __half* bt2, float* bqkv) {
    if (blockIdx.x < 2432) {
        int li = blockIdx.x * 256 + threadIdx.x;
        const float* W; __half* dst; int N, nofs, ldk;
        if (li < 16384)                  { W = Wq; dst = btq; N = 64;   nofs = 0;  ldk = 256;  }
        else if ((li -= 16384) < 16384)  { W = Wk; dst = btq; N = 64;   nofs = 64; ldk = 256;  }
        else if ((li -= 16384) < 262144) { W = W1; dst = bt1; N = 1024; nofs = 0;  ldk = 256;  }
        else if ((li -= 262144) < 262144){ W = W2; dst = bt2; N = 256;  nofs = 0;  ldk = 1024; }
        else return;
        int k = li / N, n = li % N;
        dst[(size_t)(nofs + n) * ldk + k] = __float2half_rn(W[li]);
    } else if (blockIdx.x < 2688) {
        const int d = blockIdx.x - 2432;
        const int j = threadIdx.x;
        const float* wrow = Wv + d * 256;
        float a0 = 0.f, a1 = 0.f, a2 = 0.f, a3 = 0.f;
        #pragma unroll 4
        for (int k = 0; k < 256; k += 4) {
            a0 += wrow[k + 0] * Wo[(k + 0) * 256 + j];
            a1 += wrow[k + 1] * Wo[(k + 1) * 256 + j];
            a2 += wrow[k + 2] * Wo[(k + 2) * 256 + j];
            a3 += wrow[k + 3] * Wo[(k + 3) * 256 + j];
        }
        btq[(size_t)(128 + j) * 256 + d] = __float2half_rn((a0 + a1) + (a2 + a3));
    } else {
        const int j = threadIdx.x;
        float a = 0.f;
        for (int k = 0; k < 256; k++) a += bv[k] * Wo[k * 256 + j];
        bqkv[128 + j] = a;
    }
}

// ----------------------------- gather + round --------------------------------
__global__ void gather_kernel(const float* __restrict__ x, __half* __restrict__ xg) {
    const float4* x4 = reinterpret_cast<const float4*>(x);
    int base = blockIdx.x * 1024 + threadIdx.x;
    #pragma unroll
    for (int i = 0; i < 4; i++) {
        int idx = base + i * 256;
        int m = idx >> 6, c = idx & 63;
        float4 v = x4[src_row(m) * 64 + c];
        __half2 h0 = __floats2half2_rn(v.x, v.y);
        __half2 h1 = __floats2half2_rn(v.z, v.w);
        uint2 u;
        u.x = *reinterpret_cast<uint32_t*>(&h0);
        u.y = *reinterpret_cast<uint32_t*>(&h1);
        *reinterpret_cast<uint2*>(xg + (size_t)idx * 4) = u;
    }
}

// ------------------- B-resident GEMM (K=256, MT M-tiles/CTA) -----------------
#define BC_ACHUNK 16384
#define BC_BBYTES 65536
#define BC_SMEM   (BC_BBYTES + 3 * BC_ACHUNK)
template <bool RELU, int MT>
__global__ void __launch_bounds__(256, 2)
gemm_bc(const __half* __restrict__ A, const __half* __restrict__ Bt,
        const float* __restrict__ bias, __half* __restrict__ C, int N)
{
    constexpr int K = 256;
    extern __shared__ char smem[];
    const uint32_t sb = smem_u32(smem);
    const uint32_t SM_B = sb;
    const uint32_t SM_A = sb + BC_BBYTES;

    const int tid  = threadIdx.x;
    const int lane = tid & 31, warp = tid >> 5;
    const int wm = warp >> 2, wn = warp & 3;
    const int lq = lane >> 2, lr = lane & 3;
    const int row00 = blockIdx.y * (128 * MT);
    const int n0    = blockIdx.x * 128;

    const int r_ld = tid >> 3;
    const int cseg = tid & 7;
    const uint32_t sOff = swz(r_ld * 128 + cseg * 16);

    {
        const size_t bRow0 = (size_t)(n0 + r_ld) * K;
        #pragma unroll
        for (int kt = 0; kt < 4; kt++) {
            const int kofs = kt * 64 + cseg * 8;
            #pragma unroll
            for (int i = 0; i < 4; i++)
                cp16(SM_B + kt * BC_ACHUNK + sOff + i * 4096,
                     Bt + bRow0 + (size_t)i * 32 * K + kofs);
        }
        cp_commit();
    }

    auto load_A = [&](int it, int buf) {
        const int m = it >> 2, kt = it & 3;
        const int kofs = kt * 64 + cseg * 8;
        const size_t aRow0 = (size_t)(row00 + m * 128 + r_ld) * K;
        const uint32_t aBase = SM_A + buf * BC_ACHUNK;
        #pragma unroll
        for (int i = 0; i < 4; i++)
            cp16(aBase + sOff + i * 4096, A + aRow0 + (size_t)i * 32 * K + kofs);
        cp_commit();
    };

    const int quad = lane >> 3, r8 = lane & 7;
    const int aRowL  = wm * 64 + (quad & 1) * 8 + r8;
    const int aKoffB = (quad >> 1) * 16;
    const int bRowL  = wn * 32 + (quad >> 1) * 8 + r8;
    const int bKoffB = (quad & 1) * 16;

    float acc[4][4][4];

    auto compute = [&](int buf, int kt) {
        const uint32_t aBase = SM_A + buf * BC_ACHUNK;
        const uint32_t bBase = SM_B + kt * BC_ACHUNK;
        #pragma unroll
        for (int ks = 0; ks < 4; ks++) {
            uint32_t af[4][4], bf[2][4];
            #pragma unroll
            for (int mi = 0; mi < 4; mi++) {
                int row = aRowL + mi * 16;
                ldsm4(af[mi][0], af[mi][1], af[mi][2], af[mi][3],
                      aBase + swz(row * 128 + ks * 32 + aKoffB));
            }
            #pragma unroll
            for (int nt = 0; nt < 2; nt++) {
                int row = bRowL + nt * 16;
                ldsm4(bf[nt][0], bf[nt][1], bf[nt][2], bf[nt][3],
                      bBase + swz(row * 128 + ks * 32 + bKoffB));
            }
            #pragma unroll
            for (int mi = 0; mi < 4; mi++) {
                #pragma unroll
                for (int nt = 0; nt < 2; nt++) {
                    mma_f16(acc[mi][nt * 2 + 0], af[mi], &bf[nt][0]);
                    mma_f16(acc[mi][nt * 2 + 1], af[mi], &bf[nt][2]);
                }
            }
        }
    };

    auto epilogue = [&](int m) {
        #pragma unroll
        for (int mi = 0; mi < 4; mi++) {
            #pragma unroll
            for (int ni = 0; ni < 4; ni++) {
                const int r0 = row00 + m * 128 + wm * 64 + mi * 16 + lq;
                const int c0 = n0 + wn * 32 + ni * 8 + 2 * lr;
                const float b0 = __ldg(bias + c0), b1 = __ldg(bias + c0 + 1);
                float v0 = acc[mi][ni][0] + b0;
                float v1 = acc[mi][ni][1] + b1;
                float v2 = acc[mi][ni][2] + b0;
                float v3 = acc[mi][ni][3] + b1;
                if (RELU) {
                    v0 = fmaxf(v0, 0.f); v1 = fmaxf(v1, 0.f);
                    v2 = fmaxf(v2, 0.f); v3 = fmaxf(v3, 0.f);
                }
                *reinterpret_cast<__half2*>(C + (size_t)r0 * N + c0) =
                    __floats2half2_rn(v0, v1);
                *reinterpret_cast<__half2*>(C + (size_t)(r0 + 8) * N + c0) =
                    __floats2half2_rn(v2, v3);
            }
        }
    };

    load_A(0, 0);
    load_A(1, 1);
    const int IT = MT * 4;
    for (int it = 0; it < IT; it++) {
        const int kt = it & 3, buf = it % 3;
        if (kt == 0) {
            #pragma unroll
            for (int mi = 0; mi < 4; mi++)
                #pragma unroll
                for (int ni = 0; ni < 4; ni++)
                    #pragma unroll
                    for (int j = 0; j < 4; j++) acc[mi][ni][j] = 0.f;
        }
        cp_wait<1>();
        __syncthreads();
        if (it + 2 < IT) load_A(it + 2, (it + 2) % 3);
        else cp_commit();
        compute(buf, kt);
        if (kt == 3) epilogue(it >> 2);
    }
}

// --------- fused GEMM + bias + residual + LayerNorm (+scatter), K-deep -------
#define GL_ASTG  16384
#define GL_BSTG  32768
#define GL_STG   (GL_ASTG + GL_BSTG)
#define GL_SMEM  (3 * GL_STG)
template <int K, bool SCATTER, typename OutT>
__global__ void __launch_bounds__(512, 1)
gemm_ln(const __half* __restrict__ A, const __half* __restrict__ Bt,
        const float* __restrict__ bias, const __half* __restrict__ Hres,
        const float* __restrict__ gamma, const float* __restrict__ beta,
        OutT* __restrict__ out)
{
    extern __shared__ char smem[];
    const uint32_t sb = smem_u32(smem);

    const int tid  = threadIdx.x;
    const int lane = tid & 31, warp = tid >> 5;
    const int wm = warp >> 2, wn = warp & 3;
    const int lq = lane >> 2, lr = lane & 3;
    const int row0 = blockIdx.x * 128;

    float acc[2][8][4];
    #pragma unroll
    for (int mi = 0; mi < 2; mi++)
        #pragma unroll
        for (int ni = 0; ni < 8; ni++)
            #pragma unroll
            for (int j = 0; j < 4; j++) acc[mi][ni][j] = 0.f;

    const int r_ld = tid >> 3;
    const int cseg = tid & 7;
    const uint32_t sOff = swz(r_ld * 128 + cseg * 16);

    auto load_stage = [&](int kt, int buf) {
        const int kofs = kt * 64 + cseg * 8;
        const uint32_t aBase = sb + buf * GL_STG;
        const uint32_t bBase = aBase + GL_ASTG;
        #pragma unroll
        for (int i = 0; i < 2; i++)
            cp16(aBase + sOff + i * 8192,
                 A + (size_t)(row0 + r_ld + i * 64) * K + kofs);
        #pragma unroll
        for (int i = 0; i < 4; i++)
            cp16(bBase + sOff + i * 8192,
                 Bt + (size_t)(r_ld + i * 64) * K + kofs);
        cp_commit();
    };

    const int quad = lane >> 3, r8 = lane & 7;
    const int aRowL  = wm * 32 + (quad & 1) * 8 + r8;
    const int aKoffB = (quad >> 1) * 16;
    const int bRowL  = wn * 64 + (quad >> 1) * 8 + r8;
    const int bKoffB = (quad & 1) * 16;

    auto compute = [&](int buf) {
        const uint32_t aBase = sb + buf * GL_STG;
        const uint32_t bBase = aBase + GL_ASTG;
        #pragma unroll
        for (int ks = 0; ks < 4; ks++) {
            uint32_t af[2][4], bf[4][4];
            #pragma unroll
            for (int mi = 0; mi < 2; mi++) {
                int row = aRowL + mi * 16;
                ldsm4(af[mi][0], af[mi][1], af[mi][2], af[mi][3],
                      aBase + swz(row * 128 + ks * 32 + aKoffB));
            }
            #pragma unroll
            for (int nt = 0; nt < 4; nt++) {
                int row = bRowL + nt * 16;
                ldsm4(bf[nt][0], bf[nt][1], bf[nt][2], bf[nt][3],
                      bBase + swz(row * 128 + ks * 32 + bKoffB));
            }
            #pragma unroll
            for (int mi = 0; mi < 2; mi++) {
                #pragma unroll
                for (int nt = 0; nt < 4; nt++) {
                    mma_f16(acc[mi][nt * 2 + 0], af[mi], &bf[nt][0]);
                    mma_f16(acc[mi][nt * 2 + 1], af[mi], &bf[nt][2]);
                }
            }
        }
    };

    load_stage(0, 0);
    load_stage(1, 1);
    const int KT = K >> 6;
    for (int kt = 0; kt < KT; kt++) {
        cp_wait<1>();
        __syncthreads();
        if (kt + 2 < KT) load_stage(kt + 2, (kt + 2) % 3);
        else cp_commit();
        compute(kt % 3);
    }

    __syncthreads();
    float2* rowred = reinterpret_cast<float2*>(smem);

    #pragma unroll
    for (int mi = 0; mi < 2; mi++) {
        #pragma unroll
        for (int rs = 0; rs < 2; rs++) {
            const int row_l = wm * 32 + mi * 16 + lq + rs * 8;
            const int grow  = row0 + row_l;
            float s = 0.f, sq = 0.f;
            #pragma unroll
            for (int ni = 0; ni < 8; ni++) {
                const int c0 = wn * 64 + ni * 8 + 2 * lr;
                __half2 h2 = *reinterpret_cast<const __half2*>(
                    Hres + (size_t)grow * DMODEL + c0);
                float2 fh = __half22float2(h2);
                float v0 = acc[mi][ni][rs * 2 + 0] + fh.x + __ldg(bias + c0);
                float v1 = acc[mi][ni][rs * 2 + 1] + fh.y + __ldg(bias + c0 + 1);
                acc[mi][ni][rs * 2 + 0] = v0;
                acc[mi][ni][rs * 2 + 1] = v1;
                s += v0 + v1; sq += v0 * v0 + v1 * v1;
            }
            s  += __shfl_xor_sync(0xffffffffu, s, 1);
            sq += __shfl_xor_sync(0xffffffffu, sq, 1);
            s  += __shfl_xor_sync(0xffffffffu, s, 2);
            sq += __shfl_xor_sync(0xffffffffu, sq, 2);
            if (lr == 0) rowred[row_l * 4 + wn] = make_float2(s, sq);
        }
    }
    __syncthreads();

    #pragma unroll
    for (int mi = 0; mi < 2; mi++) {
        #pragma unroll
        for (int rs = 0; rs < 2; rs++) {
            const int row_l = wm * 32 + mi * 16 + lq + rs * 8;
            const int grow  = row0 + row_l;
            float2 t0 = rowred[row_l * 4 + 0];
            float2 t1 = rowred[row_l * 4 + 1];
            float2 t2 = rowred[row_l * 4 + 2];
            float2 t3 = rowred[row_l * 4 + 3];
            const float s  = t0.x + t1.x + t2.x + t3.x;
            const float sq = t0.y + t1.y + t2.y + t3.y;
            const float mean = s * (1.f / DMODEL);
            const float var  = sq * (1.f / DMODEL) - mean * mean;
            const float rstd = rsqrtf(var + 1e-5f);
            const int orow = SCATTER ? src_row(grow) : grow;
            OutT* op = out + (size_t)orow * DMODEL;
            #pragma unroll
            for (int ni = 0; ni < 8; ni++) {
                const int c0 = wn * 64 + ni * 8 + 2 * lr;
                float o0 = (acc[mi][ni][rs * 2 + 0] - mean) * rstd * __ldg(gamma + c0)
                         + __ldg(beta + c0);
                float o1 = (acc[mi][ni][rs * 2 + 1] - mean) * rstd * __ldg(gamma + c0 + 1)
                         + __ldg(beta + c0 + 1);
                if (sizeof(OutT) == 2) {
                    *reinterpret_cast<__half2*>((__half*)op + c0) =
                        __floats2half2_rn(o0, o1);
                } else {
                    *reinterpret_cast<float2*>((float*)op + c0) = make_float2(o0, o1);
                }
            }
        }
    }
}

// ------------- attention + residual + LN1 (per window, round-14 body) --------
__global__ void __launch_bounds__(256, 5)
attn_kernel(const __half* __restrict__ qkv, const __half* __restrict__ xg,
            const float* __restrict__ bo,
            const float* __restrict__ g1, const float* __restrict__ b1,
            __half* __restrict__ h) {
    __shared__ uint32_t qs [16 * 32];
    __shared__ uint32_t ksT[32 * 17];
    __shared__ uint32_t vs [16 * 128];
    __shared__ float    sc [16][17];

    const int w = blockIdx.x, t = threadIdx.x;
    const __half* base = qkv + (size_t)w * 16 * DQKV;

    {
        int which = t >> 7;
        int vi = t & 127;
        int r = vi >> 3, c8 = (vi & 7) * 8;
        uint4 raw = *reinterpret_cast<const uint4*>(base + r * DQKV + which * 64 + c8);
        uint32_t u[4] = {raw.x, raw.y, raw.z, raw.w};
        if (which == 0) {
            #pragma unroll
            for (int p = 0; p < 4; p++) qs[r * 32 + c8 / 2 + p] = u[p];
        } else {
            #pragma unroll
            for (int p = 0; p < 4; p++) ksT[(c8 / 2 + p) * 17 + r] = u[p];
        }
    }
    #pragma unroll
    for (int it = 0; it < 2; it++) {
        int vi = t + it * 256;
        int r = vi >> 5, c8 = (vi & 31) * 8;
        uint4 raw = *reinterpret_cast<const uint4*>(base + r * DQKV + 128 + c8);
        vs[r * 128 + c8 / 2 + 0] = raw.x;
        vs[r * 128 + c8 / 2 + 1] = raw.y;
        vs[r * 128 + c8 / 2 + 2] = raw.z;
        vs[r * 128 + c8 / 2 + 3] = raw.w;
    }
    __syncthreads();

    {
        int qi = t >> 4, kj = t & 15;
        float s = 0.f;
        #pragma unroll
        for (int e2 = 0; e2 < 32; e2++) {
            float2 q = __half22float2(*reinterpret_cast<const __half2*>(&qs[qi * 32 + e2]));
            float2 k = __half22float2(*reinterpret_cast<const __half2*>(&ksT[e2 * 17 + kj]));
            s += q.x * k.x + q.y * k.y;
        }
        sc[qi][kj] = s * 0.125f;
    }
    __syncthreads();

    if (t < 16) {
        float mx = -1e30f;
        #pragma unroll
        for (int j = 0; j < 16; j++) mx = fmaxf(mx, sc[t][j]);
        float sum = 0.f;
        #pragma unroll
        for (int j = 0; j < 16; j++) { float e = __expf(sc[t][j] - mx); sc[t][j] = e; sum += e; }
        float inv = 1.f / sum;
        #pragma unroll
        for (int j = 0; j < 16; j++) sc[t][j] *= inv;
    }
    __syncthreads();

    {
        const int tp  = t >> 5;            // warp id: tokens tp, tp+8
        const int cp0 = t & 31;            // lane
        float accx[2][4], accy[2][4];
        #pragma unroll
        for (int s2 = 0; s2 < 2; s2++)
            #pragma unroll
            for (int j = 0; j < 4; j++) { accx[s2][j] = 0.f; accy[s2][j] = 0.f; }

        #pragma unroll
        for (int kk = 0; kk < 16; kk++) {
            const float a0 = sc[tp][kk];
            const float a1 = sc[tp + 8][kk];
            #pragma unroll
            for (int j = 0; j < 4; j++) {
                float2 v = __half22float2(
                    *reinterpret_cast<const __half2*>(&vs[kk * 128 + cp0 + 32 * j]));
                accx[0][j] += a0 * v.x; accy[0][j] += a0 * v.y;
                accx[1][j] += a1 * v.x; accy[1][j] += a1 * v.y;
            }
        }

        // fused: h = LN1(xg + acc + bo)
        #pragma unroll
        for (int s2 = 0; s2 < 2; s2++) {
            const int grow = w * 16 + tp + s2 * 8;
            const __half* xrow = xg + (size_t)grow * DMODEL;
            float s = 0.f, sq = 0.f;
            #pragma unroll
            for (int j = 0; j < 4; j++) {
                const int c = 2 * (cp0 + 32 * j);
                float2 fx = __half22float2(
                    *reinterpret_cast<const __half2*>(xrow + c));
                float v0 = accx[s2][j] + fx.x + __ldg(bo + c);
                float v1 = accy[s2][j] + fx.y + __ldg(bo + c + 1);
                accx[s2][j] = v0; accy[s2][j] = v1;
                s += v0 + v1; sq += v0 * v0 + v1 * v1;
            }
            #pragma unroll
            for (int off = 16; off; off >>= 1) {
                s  += __shfl_xor_sync(0xffffffffu, s,  off);
                sq += __shfl_xor_sync(0xffffffffu, sq, off);
            }
            const float mean = s * (1.f / DMODEL);
            const float var  = sq * (1.f / DMODEL) - mean * mean;
            const float rstd = rsqrtf(var + 1e-5f);
            __half* hrow = h + (size_t)grow * DMODEL;
            #pragma unroll
            for (int j = 0; j < 4; j++) {
                const int c = 2 * (cp0 + 32 * j);
                float o0 = (accx[s2][j] - mean) * rstd * __ldg(g1 + c) + __ldg(b1 + c);
                float o1 = (accy[s2][j] - mean) * rstd * __ldg(g1 + c + 1) + __ldg(b1 + c + 1);
                *reinterpret_cast<__half2*>(hrow + c) = __floats2half2_rn(o0, o1);
            }
        }
    }
}

// ------------------------------ launch --------------------------------------
extern "C" void kernel_launch(void* const* d_in, const int* in_sizes, int n_in,
                              void* d_out, int out_size) {
    const float* x   = (const float*)d_in[0];
    const float* Wq  = (const float*)d_in[1];
    const float* bq  = (const float*)d_in[2];
    const float* Wk  = (const float*)d_in[3];
    const float* bk  = (const float*)d_in[4];
    const float* Wv  = (const float*)d_in[5];
    const float* bv  = (const float*)d_in[6];
    const float* Wo  = (const float*)d_in[7];
    const float* bo  = (const float*)d_in[8];
    const float* g1  = (const float*)d_in[9];
    const float* b1  = (const float*)d_in[10];
    const float* W1  = (const float*)d_in[11];
    const float* bf1 = (const float*)d_in[12];
    const float* W2  = (const float*)d_in[13];
    const float* bf2 = (const float*)d_in[14];
    const float* g2  = (const float*)d_in[15];
    const float* b2  = (const float*)d_in[16];
    float* out = (float*)d_out;

    void *pxg, *pqkv, *ph, *pf, *pbtq, *pbt1, *pbt2, *pbq;
    cudaGetSymbolAddress(&pxg, g_xg);
    cudaGetSymbolAddress(&pqkv, g_qkv);
    cudaGetSymbolAddress(&ph,  g_h);
    cudaGetSymbolAddress(&pf,  g_f);
    cudaGetSymbolAddress(&pbtq, g_bt_qkv);
    cudaGetSymbolAddress(&pbt1, g_bt_1);
    cudaGetSymbolAddress(&pbt2, g_bt_2);
    cudaGetSymbolAddress(&pbq,  g_bqkv);
    __half* xg = (__half*)pxg; __half* qkv = (__half*)pqkv;
    __half* h = (__half*)ph; __half* f = (__half*)pf;
    __half* btq = (__half*)pbtq;
    __half* bt1 = (__half*)pbt1; __half* bt2 = (__half*)pbt2;
    float* bqkv = (float*)pbq;

    cudaFuncSetAttribute(gemm_bc<false, 4>, cudaFuncAttributeMaxDynamicSharedMemorySize, BC_SMEM);
    cudaFuncSetAttribute(gemm_bc<true,  8>, cudaFuncAttributeMaxDynamicSharedMemorySize, BC_SMEM);
    cudaFuncSetAttribute(gemm_ln<1024, true, float>, cudaFuncAttributeMaxDynamicSharedMemorySize, GL_SMEM);

    // (1) weight prep: transposes + Wvo/bvo
    prep_kernel<<<2689, 256>>>(Wq, Wk, Wv, Wo, W1, W2, bv, btq, bt1, bt2, bqkv);

    cudaMemcpyAsync(bqkv,      bq, 64 * sizeof(float), cudaMemcpyDeviceToDevice);
    cudaMemcpyAsync(bqkv + 64, bk, 64 * sizeof(float), cudaMemcpyDeviceToDevice);

    // (2) gather
    gather_kernel<<<NWIN, 256>>>(x, xg);

    // (3) qkv = xg @ [Wq | Wk | Wv@Wo]^T + [bq|bk|bvo]
    gemm_bc<false, 4><<<dim3(3, M_TOK / 512), 256, BC_SMEM>>>(xg, btq, bqkv, qkv, DQKV);

    // (4, profiled slot) attention + residual + LN1 -> h
    attn_kernel<<<NWIN, 256>>>(qkv, xg, bo, g1, b1, h);

    // (5) f = relu(h @ W1 + bf1)
    gemm_bc<true, 8><<<dim3(8, M_TOK / 1024), 256, BC_SMEM>>>(h, bt1, bf1, f, DFF);

    // (6) out = scatter(LN(h + f @ W2 + bf2))
    gemm_ln<1024, true, float><<<M_TOK / 128, 512, GL_SMEM>>>(
        f, bt2, bf2, h, g2, b2, out);
}